// round 14
// baseline (speedup 1.0000x reference)
#include <cuda_runtime.h>
#include <cuda_bf16.h>
#include <math.h>
#include <stdint.h>

// ================= scratch (device globals: allocation-free) =================
__device__ __nv_bfloat16 g_K1fh[1024];           // conv1 W hi, frag layout
__device__ __nv_bfloat16 g_K1fl[1024];           // conv1 W lo
__device__ __nv_bfloat16 g_Bh[64000];            // conv2 W hi, frag layout, lane-stride 20 words
__device__ __nv_bfloat16 g_Bl[64000];            // conv2 W lo
__device__ __nv_bfloat16 g_W1h[409600];          // fc1 W hi, frag layout
__device__ __nv_bfloat16 g_W1l[409600];          // fc1 W lo
__device__ float g_h1[4096 * 196 * 32];          // conv1 out pos-major [b][pos][ic]
__device__ __nv_bfloat16 g_Ah[4096 * 3200];      // conv2 out hi (fc1 A), K padded to 3200 (pad=0)
__device__ __nv_bfloat16 g_Al[4096 * 3200];      // conv2 out lo
__device__ float g_f1[4096 * 128];               // fc1 output

// ================= helpers =================
__device__ __forceinline__ uint32_t smem_u32(const void* p) {
    return (uint32_t)__cvta_generic_to_shared(p);
}
#define CP_ASYNC16(dst_u32, src_ptr) \
    asm volatile("cp.async.cg.shared.global [%0], [%1], 16;" :: "r"(dst_u32), "l"(src_ptr))
#define CP_COMMIT() asm volatile("cp.async.commit_group;")
#define CP_WAIT0() asm volatile("cp.async.wait_group 0;" ::: "memory")

__device__ __forceinline__ void mma_bf16(float* c, uint32_t a0, uint32_t a1,
                                         uint32_t a2, uint32_t a3,
                                         uint32_t b0, uint32_t b1) {
    asm volatile(
        "mma.sync.aligned.m16n8k16.row.col.f32.bf16.bf16.f32 "
        "{%0,%1,%2,%3}, {%4,%5,%6,%7}, {%8,%9}, {%0,%1,%2,%3};"
        : "+f"(c[0]), "+f"(c[1]), "+f"(c[2]), "+f"(c[3])
        : "r"(a0), "r"(a1), "r"(a2), "r"(a3), "r"(b0), "r"(b1));
}

__device__ __forceinline__ void pack_pair(float a, float b, uint32_t& h, uint32_t& l) {
    __nv_bfloat162 hp = __floats2bfloat162_rn(a, b);
    uint32_t hu = *(uint32_t*)&hp;
    float ra = a - __uint_as_float(hu << 16);
    float rb = b - __uint_as_float(hu & 0xFFFF0000u);
    __nv_bfloat162 lp = __floats2bfloat162_rn(ra, rb);
    h = hu;
    l = *(uint32_t*)&lp;
}

// ================= DCLS dense-kernel builders =================
// conv1: dense DCLS -> bf16 hi/lo in HMMA B-frag layout. k 0..31 (>=25 -> exact zero).
__global__ void build_k1_frag(const float* __restrict__ w1, const float* __restrict__ p1) {
    int t = blockIdx.x * 256 + threadIdx.x;
    if (t >= 1024) return;
    int k  = t >> 5;        // 0..31
    int oc = t & 31;
    float s = 0.f;
    if (k < 25) {
        int ii = k / 5, jj = k - ii * 5;
        #pragma unroll 4
        for (int kc = 0; kc < 16; kc++) {
            int e = oc * 16 + kc;
            float w  = w1[e];
            float pa = fminf(fmaxf(p1[e],       -2.f), 2.f) + 2.f;
            float pb = fminf(fmaxf(p1[512 + e], -2.f), 2.f) + 2.f;
            int i1 = (int)floorf(pa), i2 = (int)floorf(pb);
            float r1 = pa - (float)i1, r2 = pb - (float)i2;
            if (i1     == ii && i2     == jj) s += w * (1.f - r1) * (1.f - r2);
            if (i1 + 1 == ii && i2     == jj) s += w * r1 * (1.f - r2);
            if (i1     == ii && i2 + 1 == jj) s += w * (1.f - r1) * r2;
            if (i1 + 1 == ii && i2 + 1 == jj) s += w * r1 * r2;
        }
    }
    __nv_bfloat16 hi = __float2bfloat16(s);
    __nv_bfloat16 lo = __float2bfloat16(s - __bfloat162float(hi));
    int ts = k >> 4, kk = k & 15;
    int reg = kk >> 3, half = kk & 1;
    int ln  = ((kk >> 1) & 3) + (oc & 7) * 4;
    int n8  = oc >> 3;
    int word = ((ts * 4 + n8) * 2 + reg) * 32 + ln;
    g_K1fh[2 * word + half] = hi;
    g_K1fl[2 * word + half] = lo;
}

// conv2 W -> bf16 hi/lo, frag layout: chunk c(5 ksteps): word = c*3200 + (tp*32+ln)*20 + n8*2 + reg
__global__ void build_k2_frag(const float* __restrict__ w2, const float* __restrict__ p2) {
    int t = blockIdx.x * 256 + threadIdx.x;
    if (t >= 800 * 64) return;
    int k  = t >> 6;        // 0..799
    int oc = t & 63;
    int ci = k / 25; int cell = k - ci * 25;
    int ii = cell / 5, jj = cell - ii * 5;
    float s = 0.f;
    #pragma unroll 4
    for (int kc = 0; kc < 32; kc++) {
        int e = oc * 1024 + ci * 32 + kc;
        float w  = w2[e];
        float pa = fminf(fmaxf(p2[e],         -2.f), 2.f) + 2.f;
        float pb = fminf(fmaxf(p2[65536 + e], -2.f), 2.f) + 2.f;
        int i1 = (int)floorf(pa), i2 = (int)floorf(pb);
        float r1 = pa - (float)i1, r2 = pb - (float)i2;
        if (i1     == ii && i2     == jj) s += w * (1.f - r1) * (1.f - r2);
        if (i1 + 1 == ii && i2     == jj) s += w * r1 * (1.f - r2);
        if (i1     == ii && i2 + 1 == jj) s += w * (1.f - r1) * r2;
        if (i1 + 1 == ii && i2 + 1 == jj) s += w * r1 * r2;
    }
    __nv_bfloat16 hi = __float2bfloat16(s);
    __nv_bfloat16 lo = __float2bfloat16(s - __bfloat162float(hi));
    int ts = k >> 4, kk = k & 15;
    int reg = kk >> 3, half = kk & 1;
    int ln  = ((kk >> 1) & 3) + (oc & 7) * 4;
    int n8  = oc >> 3;
    int c   = ts / 5, tp = ts - c * 5;
    int w = c * 3200 + (tp * 32 + ln) * 20 + n8 * 2 + reg;
    g_Bh[2 * w + half] = hi;
    g_Bl[2 * w + half] = lo;
}

// fc1 W -> bf16 hi/lo, frag layout: word = ((ts*4+nq)*32+ln)*8 + n8l*2 + reg
__global__ void build_w1_frag(const float* __restrict__ w) {
    int t = blockIdx.x * 256 + threadIdx.x;
    if (t >= 128 * 3200) return;
    int n = t / 3200; int k = t - n * 3200;
    float v = 0.f;
    if (k < 3136) {
        int p = k >> 6, oc = k & 63;
        v = w[n * 3136 + oc * 49 + p];
    }
    __nv_bfloat16 hi = __float2bfloat16(v);
    __nv_bfloat16 lo = __float2bfloat16(v - __bfloat162float(hi));
    int ts = k >> 4, kk = k & 15;
    int reg = kk >> 3, half = kk & 1;
    int ln  = ((kk >> 1) & 3) + (n & 7) * 4;
    int n8  = n >> 3;
    int nq = n8 >> 2, n8l = n8 & 3;
    int word = ((ts * 4 + nq) * 32 + ln) * 8 + n8l * 2 + reg;
    g_W1h[2 * word + half] = hi;
    g_W1l[2 * word + half] = lo;
}

// ================= conv1: bf16-split HMMA, register pooling =================
// CTA = image, 416 threads = 13 warps. M = 4 quadrants x 208 pooled slots (196 valid).
// Invalid rows compute garbage (finite), never stored. Padded k-taps have zero weights.
__global__ __launch_bounds__(416, 1) void conv1_kernel(const float* __restrict__ x,
                                                       const float* __restrict__ b1) {
    __shared__ float sImg[1024];       // 32x32 haloed image
    __shared__ uint32_t sBh[512];      // conv1 W hi frags
    __shared__ uint32_t sBl[512];
    int b = blockIdx.x;
    int tid = threadIdx.x;
    int lane = tid & 31;
    int warp = tid >> 5;   // 0..12

    for (int i = tid; i < 1024; i += 416) sImg[i] = 0.f;
    for (int i = tid; i < 512; i += 416) {
        sBh[i] = ((const uint32_t*)g_K1fh)[i];
        sBl[i] = ((const uint32_t*)g_K1fl)[i];
    }
    __syncthreads();
    const float* xb = x + (long)b * 784;
    for (int i = tid; i < 784; i += 416) {
        int r = i / 28, c = i - r * 28;
        sImg[(r + 2) * 32 + c + 2] = xb[i];
    }
    __syncthreads();

    int pp0 = warp * 16 + (lane >> 2);
    int pp1 = pp0 + 8;
    bool v0 = pp0 < 196, v1 = pp1 < 196;
    int p0c = v0 ? pp0 : 195;              // clamp for addressing only
    int p1c = v1 ? pp1 : 195;
    int pr0 = p0c / 14, pc0 = p0c - pr0 * 14;
    int pr1 = p1c / 14, pc1 = p1c - pr1 * 14;
    int b0q[4], b1q[4];
    #pragma unroll
    for (int q = 0; q < 4; q++) {
        int qr = q >> 1, qc = q & 1;
        b0q[q] = (2 * pr0 + qr) * 32 + (2 * pc0 + qc);
        b1q[q] = (2 * pr1 + qr) * 32 + (2 * pc1 + qc);
    }
    int kq = 2 * (lane & 3);
    int off[8];
    #pragma unroll
    for (int i = 0; i < 8; i++) {
        int k = kq + (i & 1) + ((i >> 1) & 1) * 8 + (i >> 2) * 16;
        int ky = k / 5, kx = k - ky * 5;
        off[i] = (k < 25) ? ky * 32 + kx : 0;   // padded taps: weight==0, any finite A ok
    }

    float acc[4][4][4];
    #pragma unroll
    for (int q = 0; q < 4; q++)
        #pragma unroll
        for (int n8 = 0; n8 < 4; n8++)
            #pragma unroll
            for (int j = 0; j < 4; j++) acc[q][n8][j] = 0.f;

    #pragma unroll
    for (int ts = 0; ts < 2; ts++) {
        uint32_t bh[4][2], bl[4][2];
        #pragma unroll
        for (int n8 = 0; n8 < 4; n8++) {
            bh[n8][0] = sBh[((ts * 4 + n8) * 2 + 0) * 32 + lane];
            bh[n8][1] = sBh[((ts * 4 + n8) * 2 + 1) * 32 + lane];
            bl[n8][0] = sBl[((ts * 4 + n8) * 2 + 0) * 32 + lane];
            bl[n8][1] = sBl[((ts * 4 + n8) * 2 + 1) * 32 + lane];
        }
        int i0 = ts * 4;
        #pragma unroll
        for (int q = 0; q < 4; q++) {
            float a00 = sImg[b0q[q] + off[i0]];
            float a01 = sImg[b0q[q] + off[i0 + 1]];
            float a08 = sImg[b0q[q] + off[i0 + 2]];
            float a09 = sImg[b0q[q] + off[i0 + 3]];
            float a10 = sImg[b1q[q] + off[i0]];
            float a11 = sImg[b1q[q] + off[i0 + 1]];
            float a18 = sImg[b1q[q] + off[i0 + 2]];
            float a19 = sImg[b1q[q] + off[i0 + 3]];
            uint32_t ah0, ah1, ah2, ah3, al0, al1, al2, al3;
            pack_pair(a00, a01, ah0, al0);
            pack_pair(a10, a11, ah1, al1);
            pack_pair(a08, a09, ah2, al2);
            pack_pair(a18, a19, ah3, al3);
            // term-major: same-acc distance 4, per-acc order unchanged (bit-identical)
            #pragma unroll
            for (int n8 = 0; n8 < 4; n8++)
                mma_bf16(acc[q][n8], ah0, ah1, ah2, ah3, bh[n8][0], bh[n8][1]);
            #pragma unroll
            for (int n8 = 0; n8 < 4; n8++)
                mma_bf16(acc[q][n8], ah0, ah1, ah2, ah3, bl[n8][0], bl[n8][1]);
            #pragma unroll
            for (int n8 = 0; n8 < 4; n8++)
                mma_bf16(acc[q][n8], al0, al1, al2, al3, bh[n8][0], bh[n8][1]);
        }
    }

    // register pooling epilogue
    float* o = g_h1 + (long)b * 6272;
    #pragma unroll
    for (int n8 = 0; n8 < 4; n8++) {
        int oc = n8 * 8 + kq;
        float bb0 = b1[oc], bb1 = b1[oc + 1];
        if (v0) {
            float2 w;
            w.x = fmaxf(fmaxf(fmaxf(acc[0][n8][0], acc[1][n8][0]),
                              fmaxf(acc[2][n8][0], acc[3][n8][0])) + bb0, 0.f);
            w.y = fmaxf(fmaxf(fmaxf(acc[0][n8][1], acc[1][n8][1]),
                              fmaxf(acc[2][n8][1], acc[3][n8][1])) + bb1, 0.f);
            *(float2*)&o[pp0 * 32 + oc] = w;
        }
        if (v1) {
            float2 w;
            w.x = fmaxf(fmaxf(fmaxf(acc[0][n8][2], acc[1][n8][2]),
                              fmaxf(acc[2][n8][2], acc[3][n8][2])) + bb0, 0.f);
            w.y = fmaxf(fmaxf(fmaxf(acc[0][n8][3], acc[1][n8][3]),
                              fmaxf(acc[2][n8][3], acc[3][n8][3])) + bb1, 0.f);
            *(float2*)&o[pp1 * 32 + oc] = w;
        }
    }
}

// ================= conv2: bf16-split HMMA implicit GEMM =================
// CTA = image; 416 threads = 13 warps; warp = 16-row M tile (196 valid of 208).
#define C2_SMEM_BYTES (23908 * 4)

__global__ __launch_bounds__(416, 2) void conv2_kernel(const float* __restrict__ b2) {
    extern __shared__ float sm[];
    float* sImg = sm;                               // 10692
    uint32_t* sTab32 = (uint32_t*)(sm + 10692);     // 416
    uint32_t* Bbuf = (uint32_t*)(sm + 11108);       // 12800 words

    int b = blockIdx.x;
    int tid = threadIdx.x;
    int lane = tid & 31;
    int warp = tid >> 5;    // 0..12

    uint32_t BbufA = smem_u32(Bbuf);
    for (int i = tid; i < 800; i += 416) {
        CP_ASYNC16(BbufA + i * 16, (const char*)g_Bh + i * 16);
        CP_ASYNC16(BbufA + 12800 + i * 16, (const char*)g_Bl + i * 16);
    }
    CP_COMMIT();

    for (int i = tid; i < 10692; i += 416) sImg[i] = 0.f;
    if (tid < 416) {   // inline offset table: k -> (ky*18+kx)*33 + ic, packed 2 shorts/word
        uint32_t w = 0;
        #pragma unroll
        for (int h = 0; h < 2; h++) {
            int k = 2 * tid + h;
            int v = 0;
            if (k < 800) {
                int ic = k / 25; int tap = k - ic * 25;
                int ky = tap / 5, kx = tap - ky * 5;
                v = (ky * 18 + kx) * 33 + ic;
            }
            w |= ((uint32_t)(v & 0xFFFF)) << (16 * h);
        }
        sTab32[tid] = w;
    }
    __syncthreads();
    {
        const float* hb = g_h1 + (long)b * 6272;
        for (int i = tid; i < 6272; i += 416) {
            int ic = i & 31; int p = i >> 5;
            int rr = p / 14, cc = p - rr * 14;
            sImg[((rr + 2) * 18 + (cc + 2)) * 33 + ic] = hb[i];
        }
    }
    __syncthreads();

    int m0 = warp * 16 + (lane >> 2);
    int m1 = m0 + 8;
    bool vr0 = m0 < 196, vr1 = m1 < 196;
    int p0c = vr0 ? m0 : 195;              // clamp for addressing; dead rows = finite garbage
    int p1c = vr1 ? m1 : 195;
    int pr0 = p0c / 14, pc0 = p0c - pr0 * 14;
    int pr1 = p1c / 14, pc1 = p1c - pr1 * 14;
    int base0 = (pr0 * 18 + pc0) * 33;
    int base1 = (pr1 * 18 + pc1) * 33;
    int kq = 2 * (lane & 3);

    float acc[8][4];
    #pragma unroll
    for (int i = 0; i < 8; i++)
        #pragma unroll
        for (int j = 0; j < 4; j++) acc[i][j] = 0.f;

    for (int c = 0; c < 10; c++) {
        CP_WAIT0();
        __syncthreads();
        if (c < 9) {
            uint32_t dst = BbufA + ((c + 1) & 1) * 25600;
            const char* sh = (const char*)g_Bh + (c + 1) * 12800;
            const char* sl = (const char*)g_Bl + (c + 1) * 12800;
            for (int i = tid; i < 800; i += 416) {
                CP_ASYNC16(dst + i * 16, sh + i * 16);
                CP_ASYNC16(dst + 12800 + i * 16, sl + i * 16);
            }
            CP_COMMIT();
        }
        const uint32_t* Bc = Bbuf + (c & 1) * 6400;

        #pragma unroll
        for (int tp = 0; tp < 5; tp++) {
            int k0 = (c * 5 + tp) * 16 + kq;
            uint32_t t01 = sTab32[k0 >> 1];
            uint32_t t89 = sTab32[(k0 >> 1) + 4];
            int o0 = (int)(short)(t01 & 0xFFFF), o1 = (int)(short)(t01 >> 16);
            int o8 = (int)(short)(t89 & 0xFFFF), o9 = (int)(short)(t89 >> 16);
            float v00 = sImg[base0 + o0];
            float v01 = sImg[base0 + o1];
            float v08 = sImg[base0 + o8];
            float v09 = sImg[base0 + o9];
            float v10 = sImg[base1 + o0];
            float v11 = sImg[base1 + o1];
            float v18 = sImg[base1 + o8];
            float v19 = sImg[base1 + o9];

            uint32_t ah0, ah1, ah2, ah3, al0, al1, al2, al3;
            pack_pair(v00, v01, ah0, al0);
            pack_pair(v10, v11, ah1, al1);
            pack_pair(v08, v09, ah2, al2);
            pack_pair(v18, v19, ah3, al3);

            const uint32_t* bpH = Bc + (tp * 32 + lane) * 20;
            const uint32_t* bpL = bpH + 3200;
            // two n8-halves; term-major inside each half (same-acc distance 4)
            #pragma unroll
            for (int h = 0; h < 2; h++) {
                uint4 h0 = *(const uint4*)&bpH[h * 8];
                uint4 h1 = *(const uint4*)&bpH[h * 8 + 4];
                uint4 l0 = *(const uint4*)&bpL[h * 8];
                uint4 l1 = *(const uint4*)&bpL[h * 8 + 4];
                float* a0 = acc[4 * h + 0];
                float* a1 = acc[4 * h + 1];
                float* a2 = acc[4 * h + 2];
                float* a3 = acc[4 * h + 3];
                mma_bf16(a0, ah0, ah1, ah2, ah3, h0.x, h0.y);
                mma_bf16(a1, ah0, ah1, ah2, ah3, h0.z, h0.w);
                mma_bf16(a2, ah0, ah1, ah2, ah3, h1.x, h1.y);
                mma_bf16(a3, ah0, ah1, ah2, ah3, h1.z, h1.w);
                mma_bf16(a0, ah0, ah1, ah2, ah3, l0.x, l0.y);
                mma_bf16(a1, ah0, ah1, ah2, ah3, l0.z, l0.w);
                mma_bf16(a2, ah0, ah1, ah2, ah3, l1.x, l1.y);
                mma_bf16(a3, ah0, ah1, ah2, ah3, l1.z, l1.w);
                mma_bf16(a0, al0, al1, al2, al3, h0.x, h0.y);
                mma_bf16(a1, al0, al1, al2, al3, h0.z, h0.w);
                mma_bf16(a2, al0, al1, al2, al3, h1.x, h1.y);
                mma_bf16(a3, al0, al1, al2, al3, h1.z, h1.w);
            }
        }
    }

    // epilogue: acc -> smem, 2x2 pool + bias + relu, split to bf16 hi/lo [b][p*64+oc]
    __syncthreads();
    float* pool = sm;     // 196 x 66
    #pragma unroll
    for (int n8 = 0; n8 < 8; n8++) {
        int col = n8 * 8 + kq;
        if (vr0) { pool[m0 * 66 + col] = acc[n8][0]; pool[m0 * 66 + col + 1] = acc[n8][1]; }
        if (vr1) { pool[m1 * 66 + col] = acc[n8][2]; pool[m1 * 66 + col + 1] = acc[n8][3]; }
    }
    __syncthreads();
    __nv_bfloat16* outH = g_Ah + (long)b * 3200;
    __nv_bfloat16* outL = g_Al + (long)b * 3200;
    for (int i = tid; i < 3136; i += 416) {
        int oc = i & 63; int pp = i >> 6;
        int pr = pp / 7, pc = pp - pr * 7;
        int ma = (2 * pr) * 14 + 2 * pc;
        float v = fmaxf(fmaxf(pool[ma * 66 + oc],        pool[(ma + 1) * 66 + oc]),
                        fmaxf(pool[(ma + 14) * 66 + oc], pool[(ma + 15) * 66 + oc]));
        v = fmaxf(v + b2[oc], 0.f);
        __nv_bfloat16 hi = __float2bfloat16(v);
        __nv_bfloat16 lo = __float2bfloat16(v - __bfloat162float(hi));
        outH[i] = hi;
        outL[i] = lo;
    }
}

// ================= FC1: bf16-split HMMA GEMM (4096x128x3200) =================
#define FC1_SMEM_BYTES ((5632 + 20480) * 4)

__global__ __launch_bounds__(256, 1) void fc1_kernel(const float* __restrict__ bias) {
    extern __shared__ uint32_t smw[];
    uint32_t* sA = smw;            // 2 x 2816
    uint32_t* sB = smw + 5632;     // 2 x 10240
    int tid = threadIdx.x;
    int lane = tid & 31;
    int warp = tid >> 5;
    int wm = warp & 1, wn = warp >> 1;
    int mBase = blockIdx.x * 32;

    uint32_t sAaddr = smem_u32(sA);
    uint32_t sBaddr = smem_u32(sB);

    {
        for (int i = tid; i < 320; i += 256) {
            int row = i / 10, g = i - row * 10;
            long so = ((long)(mBase + row) * 3200) * 2 + g * 16;
            CP_ASYNC16(sAaddr + row * 176 + g * 16, (const char*)g_Ah + so);
            CP_ASYNC16(sAaddr + 5632 + row * 176 + g * 16, (const char*)g_Al + so);
        }
        for (int i = tid; i < 1280; i += 256) {
            CP_ASYNC16(sBaddr + i * 16, (const char*)g_W1h + i * 16);
            CP_ASYNC16(sBaddr + 20480 + i * 16, (const char*)g_W1l + i * 16);
        }
        CP_COMMIT();
    }

    float acc[4][4];
    #pragma unroll
    for (int i = 0; i < 4; i++)
        #pragma unroll
        for (int j = 0; j < 4; j++) acc[i][j] = 0.f;

    int r0w = (wm * 16 + (lane >> 2)) * 44;
    int r1w = r0w + 8 * 44;

    for (int c = 0; c < 40; c++) {
        CP_WAIT0();
        __syncthreads();
        if (c < 39) {
            int p = (c + 1) & 1;
            uint32_t dA = sAaddr + p * 11264;
            for (int i = tid; i < 320; i += 256) {
                int row = i / 10, g = i - row * 10;
                long so = ((long)(mBase + row) * 3200 + (c + 1) * 80) * 2 + g * 16;
                CP_ASYNC16(dA + row * 176 + g * 16, (const char*)g_Ah + so);
                CP_ASYNC16(dA + 5632 + row * 176 + g * 16, (const char*)g_Al + so);
            }
            uint32_t dB = sBaddr + p * 40960;
            for (int i = tid; i < 1280; i += 256) {
                CP_ASYNC16(dB + i * 16, (const char*)g_W1h + (c + 1) * 20480 + i * 16);
                CP_ASYNC16(dB + 20480 + i * 16, (const char*)g_W1l + (c + 1) * 20480 + i * 16);
            }
            CP_COMMIT();
        }
        const uint32_t* Ab = sA + (c & 1) * 2816;
        const uint32_t* Bb = sB + (c & 1) * 10240;

        #pragma unroll
        for (int tp = 0; tp < 5; tp++) {
            int aw = tp * 8 + (lane & 3);
            uint32_t ah0 = Ab[r0w + aw],        ah1 = Ab[r1w + aw];
            uint32_t ah2 = Ab[r0w + aw + 4],    ah3 = Ab[r1w + aw + 4];
            uint32_t al0 = Ab[1408 + r0w + aw],     al1 = Ab[1408 + r1w + aw];
            uint32_t al2 = Ab[1408 + r0w + aw + 4], al3 = Ab[1408 + r1w + aw + 4];
            const uint32_t* bpH = Bb + ((tp * 4 + wn) * 32 + lane) * 8;
            const uint32_t* bpL = bpH + 5120;
            uint4 h0 = *(const uint4*)&bpH[0];
            uint4 h1 = *(const uint4*)&bpH[4];
            uint4 l0 = *(const uint4*)&bpL[0];
            uint4 l1 = *(const uint4*)&bpL[4];
            // term-major (same-acc distance 4, per-acc order unchanged)
            mma_bf16(acc[0], ah0, ah1, ah2, ah3, h0.x, h0.y);
            mma_bf16(acc[1], ah0, ah1, ah2, ah3, h0.z, h0.w);
            mma_bf16(acc[2], ah0, ah1, ah2, ah3, h1.x, h1.y);
            mma_bf16(acc[3], ah0, ah1, ah2, ah3, h1.z, h1.w);
            mma_bf16(acc[0], ah0, ah1, ah2, ah3, l0.x, l0.y);
            mma_bf16(acc[1], ah0, ah1, ah2, ah3, l0.z, l0.w);
            mma_bf16(acc[2], ah0, ah1, ah2, ah3, l1.x, l1.y);
            mma_bf16(acc[3], ah0, ah1, ah2, ah3, l1.z, l1.w);
            mma_bf16(acc[0], al0, al1, al2, al3, h0.x, h0.y);
            mma_bf16(acc[1], al0, al1, al2, al3, h0.z, h0.w);
            mma_bf16(acc[2], al0, al1, al2, al3, h1.x, h1.y);
            mma_bf16(acc[3], al0, al1, al2, al3, h1.z, h1.w);
        }
    }

    int row = wm * 16 + (lane >> 2);
    int m = mBase + row;
    int colb = wn * 32 + 2 * (lane & 3);
    #pragma unroll
    for (int q = 0; q < 4; q++) {
        int n0 = colb + q * 8;
        g_f1[m * 128 + n0]           = fmaxf(acc[q][0] + bias[n0], 0.f);
        g_f1[m * 128 + n0 + 1]       = fmaxf(acc[q][1] + bias[n0 + 1], 0.f);
        g_f1[(m + 8) * 128 + n0]     = fmaxf(acc[q][2] + bias[n0], 0.f);
        g_f1[(m + 8) * 128 + n0 + 1] = fmaxf(acc[q][3] + bias[n0 + 1], 0.f);
    }
}

// ================= FC2 =================
__global__ __launch_bounds__(256) void fc2_kernel(const float* __restrict__ w,
                                                  const float* __restrict__ bias,
                                                  float* __restrict__ out) {
    int idx = blockIdx.x * 256 + threadIdx.x;
    if (idx >= 4096 * 10) return;
    int b = idx / 10, n = idx - b * 10;
    const float* h  = g_f1 + (long)b * 128;
    const float* wr = w + n * 128;
    float s = bias[n];
    #pragma unroll 8
    for (int k = 0; k < 128; k++) s += h[k] * wr[k];
    out[idx] = s;
}

// ================= launcher =================
extern "C" void kernel_launch(void* const* d_in, const int* in_sizes, int n_in,
                              void* d_out, int out_size) {
    const float* x     = (const float*)d_in[0];
    const float* w1    = (const float*)d_in[1];
    const float* p1    = (const float*)d_in[2];
    const float* b1    = (const float*)d_in[3];
    const float* w2    = (const float*)d_in[4];
    const float* p2    = (const float*)d_in[5];
    const float* b2    = (const float*)d_in[6];
    const float* fc1w  = (const float*)d_in[7];
    const float* fc1b  = (const float*)d_in[8];
    const float* fc2w  = (const float*)d_in[9];
    const float* fc2b  = (const float*)d_in[10];
    float* out = (float*)d_out;

    // launch index 3 (conv2) is the one ncu profiles
    build_k1_frag<<<4, 256>>>(w1, p1);
    build_k2_frag<<<200, 256>>>(w2, p2);
    conv1_kernel<<<4096, 416>>>(x, b1);

    cudaFuncSetAttribute(conv2_kernel, cudaFuncAttributeMaxDynamicSharedMemorySize, C2_SMEM_BYTES);
    conv2_kernel<<<4096, 416, C2_SMEM_BYTES>>>(b2);

    build_w1_frag<<<1600, 256>>>(fc1w);

    cudaFuncSetAttribute(fc1_kernel, cudaFuncAttributeMaxDynamicSharedMemorySize, FC1_SMEM_BYTES);
    fc1_kernel<<<128, 256, FC1_SMEM_BYTES>>>(fc1b);

    fc2_kernel<<<160, 256>>>(fc2w, fc2b, out);
}

// round 16
// speedup vs baseline: 1.0029x; 1.0029x over previous
#include <cuda_runtime.h>
#include <cuda_bf16.h>
#include <math.h>
#include <stdint.h>

// ================= scratch (device globals: allocation-free) =================
__device__ __nv_bfloat16 g_K1fh[1024];           // conv1 W hi, frag layout
__device__ __nv_bfloat16 g_K1fl[1024];           // conv1 W lo
__device__ __nv_bfloat16 g_Bh[64000];            // conv2 W hi, frag layout, lane-stride 20 words
__device__ __nv_bfloat16 g_Bl[64000];            // conv2 W lo
__device__ __nv_bfloat16 g_W1h[409600];          // fc1 W hi, frag layout
__device__ __nv_bfloat16 g_W1l[409600];          // fc1 W lo
__device__ float g_h1[4096 * 196 * 32];          // conv1 out pos-major [b][pos][ic]
__device__ __nv_bfloat16 g_Ah[4096 * 3200];      // conv2 out hi (fc1 A), K padded to 3200 (pad=0)
__device__ __nv_bfloat16 g_Al[4096 * 3200];      // conv2 out lo
__device__ float g_f1[4096 * 128];               // fc1 output

// ================= helpers =================
__device__ __forceinline__ uint32_t smem_u32(const void* p) {
    return (uint32_t)__cvta_generic_to_shared(p);
}
#define CP_ASYNC16(dst_u32, src_ptr) \
    asm volatile("cp.async.cg.shared.global [%0], [%1], 16;" :: "r"(dst_u32), "l"(src_ptr))
#define CP_COMMIT() asm volatile("cp.async.commit_group;")
#define CP_WAIT0() asm volatile("cp.async.wait_group 0;" ::: "memory")

__device__ __forceinline__ void mma_bf16(float* c, uint32_t a0, uint32_t a1,
                                         uint32_t a2, uint32_t a3,
                                         uint32_t b0, uint32_t b1) {
    asm volatile(
        "mma.sync.aligned.m16n8k16.row.col.f32.bf16.bf16.f32 "
        "{%0,%1,%2,%3}, {%4,%5,%6,%7}, {%8,%9}, {%0,%1,%2,%3};"
        : "+f"(c[0]), "+f"(c[1]), "+f"(c[2]), "+f"(c[3])
        : "r"(a0), "r"(a1), "r"(a2), "r"(a3), "r"(b0), "r"(b1));
}

__device__ __forceinline__ void pack_pair(float a, float b, uint32_t& h, uint32_t& l) {
    __nv_bfloat162 hp = __floats2bfloat162_rn(a, b);
    uint32_t hu = *(uint32_t*)&hp;
    float ra = a - __uint_as_float(hu << 16);
    float rb = b - __uint_as_float(hu & 0xFFFF0000u);
    __nv_bfloat162 lp = __floats2bfloat162_rn(ra, rb);
    h = hu;
    l = *(uint32_t*)&lp;
}

// ================= DCLS dense-kernel builders =================
// conv1: dense DCLS -> bf16 hi/lo in HMMA B-frag layout. k 0..31 (>=25 -> exact zero).
__global__ void build_k1_frag(const float* __restrict__ w1, const float* __restrict__ p1) {
    int t = blockIdx.x * 256 + threadIdx.x;
    if (t >= 1024) return;
    int k  = t >> 5;        // 0..31
    int oc = t & 31;
    float s = 0.f;
    if (k < 25) {
        int ii = k / 5, jj = k - ii * 5;
        #pragma unroll 4
        for (int kc = 0; kc < 16; kc++) {
            int e = oc * 16 + kc;
            float w  = w1[e];
            float pa = fminf(fmaxf(p1[e],       -2.f), 2.f) + 2.f;
            float pb = fminf(fmaxf(p1[512 + e], -2.f), 2.f) + 2.f;
            int i1 = (int)floorf(pa), i2 = (int)floorf(pb);
            float r1 = pa - (float)i1, r2 = pb - (float)i2;
            if (i1     == ii && i2     == jj) s += w * (1.f - r1) * (1.f - r2);
            if (i1 + 1 == ii && i2     == jj) s += w * r1 * (1.f - r2);
            if (i1     == ii && i2 + 1 == jj) s += w * (1.f - r1) * r2;
            if (i1 + 1 == ii && i2 + 1 == jj) s += w * r1 * r2;
        }
    }
    __nv_bfloat16 hi = __float2bfloat16(s);
    __nv_bfloat16 lo = __float2bfloat16(s - __bfloat162float(hi));
    int ts = k >> 4, kk = k & 15;
    int reg = kk >> 3, half = kk & 1;
    int ln  = ((kk >> 1) & 3) + (oc & 7) * 4;
    int n8  = oc >> 3;
    int word = ((ts * 4 + n8) * 2 + reg) * 32 + ln;
    g_K1fh[2 * word + half] = hi;
    g_K1fl[2 * word + half] = lo;
}

// conv2 W -> bf16 hi/lo, frag layout: chunk c(5 ksteps): word = c*3200 + (tp*32+ln)*20 + n8*2 + reg
__global__ void build_k2_frag(const float* __restrict__ w2, const float* __restrict__ p2) {
    int t = blockIdx.x * 256 + threadIdx.x;
    if (t >= 800 * 64) return;
    int k  = t >> 6;        // 0..799
    int oc = t & 63;
    int ci = k / 25; int cell = k - ci * 25;
    int ii = cell / 5, jj = cell - ii * 5;
    float s = 0.f;
    #pragma unroll 4
    for (int kc = 0; kc < 32; kc++) {
        int e = oc * 1024 + ci * 32 + kc;
        float w  = w2[e];
        float pa = fminf(fmaxf(p2[e],         -2.f), 2.f) + 2.f;
        float pb = fminf(fmaxf(p2[65536 + e], -2.f), 2.f) + 2.f;
        int i1 = (int)floorf(pa), i2 = (int)floorf(pb);
        float r1 = pa - (float)i1, r2 = pb - (float)i2;
        if (i1     == ii && i2     == jj) s += w * (1.f - r1) * (1.f - r2);
        if (i1 + 1 == ii && i2     == jj) s += w * r1 * (1.f - r2);
        if (i1     == ii && i2 + 1 == jj) s += w * (1.f - r1) * r2;
        if (i1 + 1 == ii && i2 + 1 == jj) s += w * r1 * r2;
    }
    __nv_bfloat16 hi = __float2bfloat16(s);
    __nv_bfloat16 lo = __float2bfloat16(s - __bfloat162float(hi));
    int ts = k >> 4, kk = k & 15;
    int reg = kk >> 3, half = kk & 1;
    int ln  = ((kk >> 1) & 3) + (oc & 7) * 4;
    int n8  = oc >> 3;
    int c   = ts / 5, tp = ts - c * 5;
    int w = c * 3200 + (tp * 32 + ln) * 20 + n8 * 2 + reg;
    g_Bh[2 * w + half] = hi;
    g_Bl[2 * w + half] = lo;
}

// fc1 W -> bf16 hi/lo, frag layout: word = ((ts*4+nq)*32+ln)*8 + n8l*2 + reg
__global__ void build_w1_frag(const float* __restrict__ w) {
    int t = blockIdx.x * 256 + threadIdx.x;
    if (t >= 128 * 3200) return;
    int n = t / 3200; int k = t - n * 3200;
    float v = 0.f;
    if (k < 3136) {
        int p = k >> 6, oc = k & 63;
        v = w[n * 3136 + oc * 49 + p];
    }
    __nv_bfloat16 hi = __float2bfloat16(v);
    __nv_bfloat16 lo = __float2bfloat16(v - __bfloat162float(hi));
    int ts = k >> 4, kk = k & 15;
    int reg = kk >> 3, half = kk & 1;
    int ln  = ((kk >> 1) & 3) + (n & 7) * 4;
    int n8  = n >> 3;
    int nq = n8 >> 2, n8l = n8 & 3;
    int word = ((ts * 4 + nq) * 32 + ln) * 8 + n8l * 2 + reg;
    g_W1h[2 * word + half] = hi;
    g_W1l[2 * word + half] = lo;
}

// ================= conv1: bf16-split HMMA, register pooling =================
__global__ __launch_bounds__(416, 1) void conv1_kernel(const float* __restrict__ x,
                                                       const float* __restrict__ b1) {
    __shared__ float sImg[1024];       // 32x32 haloed image
    __shared__ uint32_t sBh[512];
    __shared__ uint32_t sBl[512];
    int b = blockIdx.x;
    int tid = threadIdx.x;
    int lane = tid & 31;
    int warp = tid >> 5;   // 0..12

    for (int i = tid; i < 1024; i += 416) sImg[i] = 0.f;
    for (int i = tid; i < 512; i += 416) {
        sBh[i] = ((const uint32_t*)g_K1fh)[i];
        sBl[i] = ((const uint32_t*)g_K1fl)[i];
    }
    __syncthreads();
    const float* xb = x + (long)b * 784;
    for (int i = tid; i < 784; i += 416) {
        int r = i / 28, c = i - r * 28;
        sImg[(r + 2) * 32 + c + 2] = xb[i];
    }
    __syncthreads();

    int pp0 = warp * 16 + (lane >> 2);
    int pp1 = pp0 + 8;
    bool v0 = pp0 < 196, v1 = pp1 < 196;
    int p0c = v0 ? pp0 : 195;
    int p1c = v1 ? pp1 : 195;
    int pr0 = p0c / 14, pc0 = p0c - pr0 * 14;
    int pr1 = p1c / 14, pc1 = p1c - pr1 * 14;
    int b0q[4], b1q[4];
    #pragma unroll
    for (int q = 0; q < 4; q++) {
        int qr = q >> 1, qc = q & 1;
        b0q[q] = (2 * pr0 + qr) * 32 + (2 * pc0 + qc);
        b1q[q] = (2 * pr1 + qr) * 32 + (2 * pc1 + qc);
    }
    int kq = 2 * (lane & 3);
    int off[8];
    #pragma unroll
    for (int i = 0; i < 8; i++) {
        int k = kq + (i & 1) + ((i >> 1) & 1) * 8 + (i >> 2) * 16;
        int ky = k / 5, kx = k - ky * 5;
        off[i] = (k < 25) ? ky * 32 + kx : 0;
    }

    float acc[4][4][4];
    #pragma unroll
    for (int q = 0; q < 4; q++)
        #pragma unroll
        for (int n8 = 0; n8 < 4; n8++)
            #pragma unroll
            for (int j = 0; j < 4; j++) acc[q][n8][j] = 0.f;

    #pragma unroll
    for (int ts = 0; ts < 2; ts++) {
        uint32_t bh[4][2], bl[4][2];
        #pragma unroll
        for (int n8 = 0; n8 < 4; n8++) {
            bh[n8][0] = sBh[((ts * 4 + n8) * 2 + 0) * 32 + lane];
            bh[n8][1] = sBh[((ts * 4 + n8) * 2 + 1) * 32 + lane];
            bl[n8][0] = sBl[((ts * 4 + n8) * 2 + 0) * 32 + lane];
            bl[n8][1] = sBl[((ts * 4 + n8) * 2 + 1) * 32 + lane];
        }
        int i0 = ts * 4;
        #pragma unroll
        for (int q = 0; q < 4; q++) {
            float a00 = sImg[b0q[q] + off[i0]];
            float a01 = sImg[b0q[q] + off[i0 + 1]];
            float a08 = sImg[b0q[q] + off[i0 + 2]];
            float a09 = sImg[b0q[q] + off[i0 + 3]];
            float a10 = sImg[b1q[q] + off[i0]];
            float a11 = sImg[b1q[q] + off[i0 + 1]];
            float a18 = sImg[b1q[q] + off[i0 + 2]];
            float a19 = sImg[b1q[q] + off[i0 + 3]];
            uint32_t ah0, ah1, ah2, ah3, al0, al1, al2, al3;
            pack_pair(a00, a01, ah0, al0);
            pack_pair(a10, a11, ah1, al1);
            pack_pair(a08, a09, ah2, al2);
            pack_pair(a18, a19, ah3, al3);
            #pragma unroll
            for (int n8 = 0; n8 < 4; n8++) {
                mma_bf16(acc[q][n8], ah0, ah1, ah2, ah3, bh[n8][0], bh[n8][1]);
                mma_bf16(acc[q][n8], ah0, ah1, ah2, ah3, bl[n8][0], bl[n8][1]);
                mma_bf16(acc[q][n8], al0, al1, al2, al3, bh[n8][0], bh[n8][1]);
            }
        }
    }

    // register pooling epilogue
    float* o = g_h1 + (long)b * 6272;
    #pragma unroll
    for (int n8 = 0; n8 < 4; n8++) {
        int oc = n8 * 8 + kq;
        float bb0 = b1[oc], bb1 = b1[oc + 1];
        if (v0) {
            float2 w;
            w.x = fmaxf(fmaxf(fmaxf(acc[0][n8][0], acc[1][n8][0]),
                              fmaxf(acc[2][n8][0], acc[3][n8][0])) + bb0, 0.f);
            w.y = fmaxf(fmaxf(fmaxf(acc[0][n8][1], acc[1][n8][1]),
                              fmaxf(acc[2][n8][1], acc[3][n8][1])) + bb1, 0.f);
            *(float2*)&o[pp0 * 32 + oc] = w;
        }
        if (v1) {
            float2 w;
            w.x = fmaxf(fmaxf(fmaxf(acc[0][n8][2], acc[1][n8][2]),
                              fmaxf(acc[2][n8][2], acc[3][n8][2])) + bb0, 0.f);
            w.y = fmaxf(fmaxf(fmaxf(acc[0][n8][3], acc[1][n8][3]),
                              fmaxf(acc[2][n8][3], acc[3][n8][3])) + bb1, 0.f);
            *(float2*)&o[pp1 * 32 + oc] = w;
        }
    }
}

// ================= conv2: bf16-split HMMA implicit GEMM =================
// CTA = image; 416 threads = 13 warps; warp = 16-row M tile (196 valid of 208).
// A-gather software-pipelined one kstep ahead (sImg is immutable during mainloop).
#define C2_SMEM_BYTES (23908 * 4)

__global__ __launch_bounds__(416, 2) void conv2_kernel(const float* __restrict__ b2) {
    extern __shared__ float sm[];
    float* sImg = sm;                               // 10692
    uint32_t* sTab32 = (uint32_t*)(sm + 10692);     // 416
    uint32_t* Bbuf = (uint32_t*)(sm + 11108);       // 12800 words

    int b = blockIdx.x;
    int tid = threadIdx.x;
    int lane = tid & 31;
    int warp = tid >> 5;    // 0..12

    uint32_t BbufA = smem_u32(Bbuf);
    for (int i = tid; i < 800; i += 416) {
        CP_ASYNC16(BbufA + i * 16, (const char*)g_Bh + i * 16);
        CP_ASYNC16(BbufA + 12800 + i * 16, (const char*)g_Bl + i * 16);
    }
    CP_COMMIT();

    for (int i = tid; i < 10692; i += 416) sImg[i] = 0.f;
    if (tid < 416) {   // inline offset table, packed 2 shorts/word
        uint32_t w = 0;
        #pragma unroll
        for (int h = 0; h < 2; h++) {
            int k = 2 * tid + h;
            int v = 0;
            if (k < 800) {
                int ic = k / 25; int tap = k - ic * 25;
                int ky = tap / 5, kx = tap - ky * 5;
                v = (ky * 18 + kx) * 33 + ic;
            }
            w |= ((uint32_t)(v & 0xFFFF)) << (16 * h);
        }
        sTab32[tid] = w;
    }
    __syncthreads();
    {
        const float* hb = g_h1 + (long)b * 6272;
        for (int i = tid; i < 6272; i += 416) {
            int ic = i & 31; int p = i >> 5;
            int rr = p / 14, cc = p - rr * 14;
            sImg[((rr + 2) * 18 + (cc + 2)) * 33 + ic] = hb[i];
        }
    }
    __syncthreads();

    int m0 = warp * 16 + (lane >> 2);
    int m1 = m0 + 8;
    bool vr0 = m0 < 196, vr1 = m1 < 196;
    int p0c = vr0 ? m0 : 195;
    int p1c = vr1 ? m1 : 195;
    int pr0 = p0c / 14, pc0 = p0c - pr0 * 14;
    int pr1 = p1c / 14, pc1 = p1c - pr1 * 14;
    int base0 = (pr0 * 18 + pc0) * 33;
    int base1 = (pr1 * 18 + pc1) * 33;
    int kq = 2 * (lane & 3);

    // gather of kstep ts -> 8 floats (sImg immutable during mainloop)
    #define C2_GATHER(ts_, dst) do {                                        \
        int kg = (ts_) * 16 + kq;                                           \
        uint32_t t01 = sTab32[kg >> 1];                                     \
        uint32_t t89 = sTab32[(kg >> 1) + 4];                               \
        int o0 = (int)(short)(t01 & 0xFFFF), o1 = (int)(short)(t01 >> 16);  \
        int o8 = (int)(short)(t89 & 0xFFFF), o9 = (int)(short)(t89 >> 16);  \
        (dst)[0] = sImg[base0 + o0]; (dst)[1] = sImg[base0 + o1];           \
        (dst)[2] = sImg[base0 + o8]; (dst)[3] = sImg[base0 + o9];           \
        (dst)[4] = sImg[base1 + o0]; (dst)[5] = sImg[base1 + o1];           \
        (dst)[6] = sImg[base1 + o8]; (dst)[7] = sImg[base1 + o9];           \
    } while (0)

    float acc[8][4];
    #pragma unroll
    for (int i = 0; i < 8; i++)
        #pragma unroll
        for (int j = 0; j < 4; j++) acc[i][j] = 0.f;

    float pv[8];
    C2_GATHER(0, pv);     // prime the pipeline

    for (int c = 0; c < 10; c++) {
        CP_WAIT0();
        __syncthreads();
        if (c < 9) {
            uint32_t dst = BbufA + ((c + 1) & 1) * 25600;
            const char* sh = (const char*)g_Bh + (c + 1) * 12800;
            const char* sl = (const char*)g_Bl + (c + 1) * 12800;
            for (int i = tid; i < 800; i += 416) {
                CP_ASYNC16(dst + i * 16, sh + i * 16);
                CP_ASYNC16(dst + 12800 + i * 16, sl + i * 16);
            }
            CP_COMMIT();
        }
        const uint32_t* Bc = Bbuf + (c & 1) * 6400;

        #pragma unroll
        for (int tp = 0; tp < 5; tp++) {
            // pack current gather into frags (frees pv for the next prefetch)
            uint32_t ah0, ah1, ah2, ah3, al0, al1, al2, al3;
            pack_pair(pv[0], pv[1], ah0, al0);
            pack_pair(pv[4], pv[5], ah1, al1);
            pack_pair(pv[2], pv[3], ah2, al2);
            pack_pair(pv[6], pv[7], ah3, al3);

            // prefetch next kstep's gather: overlaps the MMA burst below
            if (tp < 4)      C2_GATHER(c * 5 + tp + 1, pv);
            else if (c < 9)  C2_GATHER((c + 1) * 5, pv);

            const uint32_t* bpH = Bc + (tp * 32 + lane) * 20;
            const uint32_t* bpL = bpH + 3200;
            #pragma unroll
            for (int h = 0; h < 2; h++) {
                uint4 h4a = *(const uint4*)&bpH[h * 8];
                uint4 h4b = *(const uint4*)&bpH[h * 8 + 4];
                uint4 l4a = *(const uint4*)&bpL[h * 8];
                uint4 l4b = *(const uint4*)&bpL[h * 8 + 4];
                float* a0 = acc[4 * h + 0];
                float* a1 = acc[4 * h + 1];
                float* a2 = acc[4 * h + 2];
                float* a3 = acc[4 * h + 3];
                mma_bf16(a0, ah0, ah1, ah2, ah3, h4a.x, h4a.y);
                mma_bf16(a0, ah0, ah1, ah2, ah3, l4a.x, l4a.y);
                mma_bf16(a0, al0, al1, al2, al3, h4a.x, h4a.y);
                mma_bf16(a1, ah0, ah1, ah2, ah3, h4a.z, h4a.w);
                mma_bf16(a1, ah0, ah1, ah2, ah3, l4a.z, l4a.w);
                mma_bf16(a1, al0, al1, al2, al3, h4a.z, h4a.w);
                mma_bf16(a2, ah0, ah1, ah2, ah3, h4b.x, h4b.y);
                mma_bf16(a2, ah0, ah1, ah2, ah3, l4b.x, l4b.y);
                mma_bf16(a2, al0, al1, al2, al3, h4b.x, h4b.y);
                mma_bf16(a3, ah0, ah1, ah2, ah3, h4b.z, h4b.w);
                mma_bf16(a3, ah0, ah1, ah2, ah3, l4b.z, l4b.w);
                mma_bf16(a3, al0, al1, al2, al3, h4b.z, h4b.w);
            }
        }
    }
    #undef C2_GATHER

    // epilogue: acc -> smem, 2x2 pool + bias + relu, split to bf16 hi/lo [b][p*64+oc]
    __syncthreads();
    float* pool = sm;     // 196 x 66
    #pragma unroll
    for (int n8 = 0; n8 < 8; n8++) {
        int col = n8 * 8 + kq;
        if (vr0) { pool[m0 * 66 + col] = acc[n8][0]; pool[m0 * 66 + col + 1] = acc[n8][1]; }
        if (vr1) { pool[m1 * 66 + col] = acc[n8][2]; pool[m1 * 66 + col + 1] = acc[n8][3]; }
    }
    __syncthreads();
    __nv_bfloat16* outH = g_Ah + (long)b * 3200;
    __nv_bfloat16* outL = g_Al + (long)b * 3200;
    for (int i = tid; i < 3136; i += 416) {
        int oc = i & 63; int pp = i >> 6;
        int pr = pp / 7, pc = pp - pr * 7;
        int ma = (2 * pr) * 14 + 2 * pc;
        float v = fmaxf(fmaxf(pool[ma * 66 + oc],        pool[(ma + 1) * 66 + oc]),
                        fmaxf(pool[(ma + 14) * 66 + oc], pool[(ma + 15) * 66 + oc]));
        v = fmaxf(v + b2[oc], 0.f);
        __nv_bfloat16 hi = __float2bfloat16(v);
        __nv_bfloat16 lo = __float2bfloat16(v - __bfloat162float(hi));
        outH[i] = hi;
        outL[i] = lo;
    }
}

// ================= FC1: bf16-split HMMA GEMM (4096x128x3200) =================
#define FC1_SMEM_BYTES ((5632 + 20480) * 4)

__global__ __launch_bounds__(256, 1) void fc1_kernel(const float* __restrict__ bias) {
    extern __shared__ uint32_t smw[];
    uint32_t* sA = smw;            // 2 x 2816
    uint32_t* sB = smw + 5632;     // 2 x 10240
    int tid = threadIdx.x;
    int lane = tid & 31;
    int warp = tid >> 5;
    int wm = warp & 1, wn = warp >> 1;
    int mBase = blockIdx.x * 32;

    uint32_t sAaddr = smem_u32(sA);
    uint32_t sBaddr = smem_u32(sB);

    {
        for (int i = tid; i < 320; i += 256) {
            int row = i / 10, g = i - row * 10;
            long so = ((long)(mBase + row) * 3200) * 2 + g * 16;
            CP_ASYNC16(sAaddr + row * 176 + g * 16, (const char*)g_Ah + so);
            CP_ASYNC16(sAaddr + 5632 + row * 176 + g * 16, (const char*)g_Al + so);
        }
        for (int i = tid; i < 1280; i += 256) {
            CP_ASYNC16(sBaddr + i * 16, (const char*)g_W1h + i * 16);
            CP_ASYNC16(sBaddr + 20480 + i * 16, (const char*)g_W1l + i * 16);
        }
        CP_COMMIT();
    }

    float acc[4][4];
    #pragma unroll
    for (int i = 0; i < 4; i++)
        #pragma unroll
        for (int j = 0; j < 4; j++) acc[i][j] = 0.f;

    int r0w = (wm * 16 + (lane >> 2)) * 44;
    int r1w = r0w + 8 * 44;

    for (int c = 0; c < 40; c++) {
        CP_WAIT0();
        __syncthreads();
        if (c < 39) {
            int p = (c + 1) & 1;
            uint32_t dA = sAaddr + p * 11264;
            for (int i = tid; i < 320; i += 256) {
                int row = i / 10, g = i - row * 10;
                long so = ((long)(mBase + row) * 3200 + (c + 1) * 80) * 2 + g * 16;
                CP_ASYNC16(dA + row * 176 + g * 16, (const char*)g_Ah + so);
                CP_ASYNC16(dA + 5632 + row * 176 + g * 16, (const char*)g_Al + so);
            }
            uint32_t dB = sBaddr + p * 40960;
            for (int i = tid; i < 1280; i += 256) {
                CP_ASYNC16(dB + i * 16, (const char*)g_W1h + (c + 1) * 20480 + i * 16);
                CP_ASYNC16(dB + 20480 + i * 16, (const char*)g_W1l + (c + 1) * 20480 + i * 16);
            }
            CP_COMMIT();
        }
        const uint32_t* Ab = sA + (c & 1) * 2816;
        const uint32_t* Bb = sB + (c & 1) * 10240;

        #pragma unroll
        for (int tp = 0; tp < 5; tp++) {
            int aw = tp * 8 + (lane & 3);
            uint32_t ah0 = Ab[r0w + aw],        ah1 = Ab[r1w + aw];
            uint32_t ah2 = Ab[r0w + aw + 4],    ah3 = Ab[r1w + aw + 4];
            uint32_t al0 = Ab[1408 + r0w + aw],     al1 = Ab[1408 + r1w + aw];
            uint32_t al2 = Ab[1408 + r0w + aw + 4], al3 = Ab[1408 + r1w + aw + 4];
            const uint32_t* bpH = Bb + ((tp * 4 + wn) * 32 + lane) * 8;
            const uint32_t* bpL = bpH + 5120;
            uint4 h0 = *(const uint4*)&bpH[0];
            uint4 h1 = *(const uint4*)&bpH[4];
            uint4 l0 = *(const uint4*)&bpL[0];
            uint4 l1 = *(const uint4*)&bpL[4];
            mma_bf16(acc[0], ah0, ah1, ah2, ah3, h0.x, h0.y);
            mma_bf16(acc[1], ah0, ah1, ah2, ah3, h0.z, h0.w);
            mma_bf16(acc[2], ah0, ah1, ah2, ah3, h1.x, h1.y);
            mma_bf16(acc[3], ah0, ah1, ah2, ah3, h1.z, h1.w);
            mma_bf16(acc[0], ah0, ah1, ah2, ah3, l0.x, l0.y);
            mma_bf16(acc[1], ah0, ah1, ah2, ah3, l0.z, l0.w);
            mma_bf16(acc[2], ah0, ah1, ah2, ah3, l1.x, l1.y);
            mma_bf16(acc[3], ah0, ah1, ah2, ah3, l1.z, l1.w);
            mma_bf16(acc[0], al0, al1, al2, al3, h0.x, h0.y);
            mma_bf16(acc[1], al0, al1, al2, al3, h0.z, h0.w);
            mma_bf16(acc[2], al0, al1, al2, al3, h1.x, h1.y);
            mma_bf16(acc[3], al0, al1, al2, al3, h1.z, h1.w);
        }
    }

    int row = wm * 16 + (lane >> 2);
    int m = mBase + row;
    int colb = wn * 32 + 2 * (lane & 3);
    #pragma unroll
    for (int q = 0; q < 4; q++) {
        int n0 = colb + q * 8;
        g_f1[m * 128 + n0]           = fmaxf(acc[q][0] + bias[n0], 0.f);
        g_f1[m * 128 + n0 + 1]       = fmaxf(acc[q][1] + bias[n0 + 1], 0.f);
        g_f1[(m + 8) * 128 + n0]     = fmaxf(acc[q][2] + bias[n0], 0.f);
        g_f1[(m + 8) * 128 + n0 + 1] = fmaxf(acc[q][3] + bias[n0 + 1], 0.f);
    }
}

// ================= FC2 =================
__global__ __launch_bounds__(256) void fc2_kernel(const float* __restrict__ w,
                                                  const float* __restrict__ bias,
                                                  float* __restrict__ out) {
    int idx = blockIdx.x * 256 + threadIdx.x;
    if (idx >= 4096 * 10) return;
    int b = idx / 10, n = idx - b * 10;
    const float* h  = g_f1 + (long)b * 128;
    const float* wr = w + n * 128;
    float s = bias[n];
    #pragma unroll 8
    for (int k = 0; k < 128; k++) s += h[k] * wr[k];
    out[idx] = s;
}

// ================= launcher =================
extern "C" void kernel_launch(void* const* d_in, const int* in_sizes, int n_in,
                              void* d_out, int out_size) {
    const float* x     = (const float*)d_in[0];
    const float* w1    = (const float*)d_in[1];
    const float* p1    = (const float*)d_in[2];
    const float* b1    = (const float*)d_in[3];
    const float* w2    = (const float*)d_in[4];
    const float* p2    = (const float*)d_in[5];
    const float* b2    = (const float*)d_in[6];
    const float* fc1w  = (const float*)d_in[7];
    const float* fc1b  = (const float*)d_in[8];
    const float* fc2w  = (const float*)d_in[9];
    const float* fc2b  = (const float*)d_in[10];
    float* out = (float*)d_out;

    // launch index 3 (conv2) is the one ncu profiles
    build_k1_frag<<<4, 256>>>(w1, p1);
    build_k2_frag<<<200, 256>>>(w2, p2);
    conv1_kernel<<<4096, 416>>>(x, b1);

    cudaFuncSetAttribute(conv2_kernel, cudaFuncAttributeMaxDynamicSharedMemorySize, C2_SMEM_BYTES);
    conv2_kernel<<<4096, 416, C2_SMEM_BYTES>>>(b2);

    build_w1_frag<<<1600, 256>>>(fc1w);

    cudaFuncSetAttribute(fc1_kernel, cudaFuncAttributeMaxDynamicSharedMemorySize, FC1_SMEM_BYTES);
    fc1_kernel<<<128, 256, FC1_SMEM_BYTES>>>(fc1b);

    fc2_kernel<<<160, 256>>>(fc2w, fc2b, out);
}